// round 11
// baseline (speedup 1.0000x reference)
#include <cuda_runtime.h>
#include <cuda_fp16.h>
#include <cstdint>

#define Bsz 16384
#define Cn  8
#define Dd  256
#define H0n 512
#define H1n 256

// ---------------- scratch (device statics) ----------------
__device__ __align__(16) __half g_xh  [Bsz][Dd];           // 8MB   x fp16
__device__ __align__(16) __half g_w0h [Cn][H0n][Dd];       // 2MB   w0 fp16
__device__ __align__(16) __half g_w1h [Cn][H1n][H0n];      // 2MB   w1 fp16

// ---------------- prep: x, w0, w1 convert, one launch ----------------
__device__ __forceinline__ uint4 cvt8h(const float* s) {
    uint32_t h[4];
    #pragma unroll
    for (int i = 0; i < 4; i++) {
        __half h0 = __float2half_rn(s[2*i]), h1 = __float2half_rn(s[2*i+1]);
        h[i] = (uint32_t)__half_as_ushort(h0) | ((uint32_t)__half_as_ushort(h1) << 16);
    }
    return make_uint4(h[0], h[1], h[2], h[3]);
}

__global__ void prep_all(const float* __restrict__ x,
                         const float* __restrict__ W0, const float* __restrict__ W1) {
    int u = blockIdx.x * blockDim.x + threadIdx.x;   // 786432 total
    float buf[8];
    if (u < 524288) {                                 // x
        int k8 = u & 31, b = u >> 5;
        *(float4*)(buf)   = *(const float4*)(x + (size_t)b * Dd + k8 * 8);
        *(float4*)(buf+4) = *(const float4*)(x + (size_t)b * Dd + k8 * 8 + 4);
        *(uint4*)&g_xh[b][k8 * 8] = cvt8h(buf);
    } else if (u < 655360) {                          // w0
        int v = u - 524288;
        int k8 = v & 31, n = (v >> 5) & 511, c = v >> 14;
        const float* src = W0 + ((size_t)c * H0n + n) * Dd + k8 * 8;
        *(float4*)(buf)   = *(const float4*)(src);
        *(float4*)(buf+4) = *(const float4*)(src + 4);
        *(uint4*)&g_w0h[c][n][k8 * 8] = cvt8h(buf);
    } else {                                          // w1
        int v = u - 655360;
        int k8 = v & 63, n = (v >> 6) & 255, c = v >> 14;
        const float* src = W1 + ((size_t)c * H1n + n) * H0n + k8 * 8;
        *(float4*)(buf)   = *(const float4*)(src);
        *(float4*)(buf+4) = *(const float4*)(src + 4);
        *(uint4*)&g_w1h[c][n][k8 * 8] = cvt8h(buf);
    }
}

// ---------------- machinery ----------------
__device__ __forceinline__ uint32_t smem_u32(const void* p) {
    uint32_t a;
    asm("{ .reg .u64 t; cvta.to.shared.u64 t, %1; cvt.u32.u64 %0, t; }" : "=r"(a) : "l"(p));
    return a;
}
#define CP16(dst, src) asm volatile("cp.async.cg.shared.global [%0], [%1], 16;" :: "r"(dst), "l"(src))
#define CP_COMMIT()    asm volatile("cp.async.commit_group;" ::: "memory")
#define CP_WAIT0()     asm volatile("cp.async.wait_group 0;" ::: "memory")
#define LDSM4(r, a) \
    asm volatile("ldmatrix.sync.aligned.m8n8.x4.shared.b16 {%0,%1,%2,%3}, [%4];" \
        : "=r"((r)[0]), "=r"((r)[1]), "=r"((r)[2]), "=r"((r)[3]) : "r"(a))
// fp16-accumulate HMMA: D,C are 2 packed b32 regs (4 halves)
#define MMA_H(d, a, b0, b1) \
    asm volatile("mma.sync.aligned.m16n8k16.row.col.f16.f16.f16.f16 " \
        "{%0,%1}, {%2,%3,%4,%5}, {%6,%7}, {%0,%1};" \
        : "+r"((d)[0]), "+r"((d)[1]) \
        : "r"((a)[0]), "r"((a)[1]), "r"((a)[2]), "r"((a)[3]), "r"(b0), "r"(b1))

__device__ __forceinline__ float2 h2f2(uint32_t u) {
    __half2 h = *(__half2*)&u;
    return __half22float2(h);
}

// ---- smem layout (bytes) ----
// h0 tile:  [0, 131072)              128 rows x 1024B (512 fp16), XOR-swizzled rows
// ring:     [131072, 229376)         2 stages x 48KB; stage: A 16KB @ +0, B 32KB @ +16384
// red:      reuses ring stage0 A-slot
#define H0S   0
#define RING  131072
#define STG   49152
#define SMEM_TOTAL 229376

#define LOADB(sB) do {                                                         \
    _Pragma("unroll")                                                          \
    for (int ng = 0; ng < 4; ng++) {                                           \
        int row = wn0 + ng * 16 + (lane & 7) + ((lane >> 4) << 3);             \
        int g   = s16 * 2 + ((lane >> 3) & 1);                                 \
        LDSM4(bfr[ng], (sB) + row * 128 + ((g ^ (row & 7)) << 4));             \
    }                                                                          \
} while (0)

#define DOMMA(accset) \
    _Pragma("unroll")                                                          \
    for (int mt = 0; mt < 4; mt++)                                             \
        _Pragma("unroll")                                                      \
        for (int ni = 0; ni < 8; ni++)                                         \
            MMA_H((accset)[mt][ni], afr[mt], bfr[ni >> 1][(ni & 1) * 2],       \
                  bfr[ni >> 1][(ni & 1) * 2 + 1])

#define ACC_ZERO() do {                                                        \
    _Pragma("unroll")                                                          \
    for (int q = 0; q < 2; q++)                                                \
        _Pragma("unroll")                                                      \
        for (int a = 0; a < 4; a++)                                            \
            _Pragma("unroll")                                                  \
            for (int b = 0; b < 8; b++) {                                      \
                acch[q][a][b][0] = 0u; acch[q][a][b][1] = 0u;                  \
            }                                                                  \
} while (0)

// ============ fused: h0 = relu(x@w0^T+b0) in smem; out = relu(h0@w1^T+b1).w2 + b2 ============
__global__ void __launch_bounds__(256, 1)
fused(const float* __restrict__ b0g, const float* __restrict__ b1g,
      const float* __restrict__ w2g, const float* __restrict__ b2g,
      float* __restrict__ out)
{
    extern __shared__ __align__(128) uint8_t sm[];
    const uint32_t sb = smem_u32(sm);
    const int tid = threadIdx.x, lane = tid & 31, wid = tid >> 5;
    const int wm0 = (wid & 1) * 64, wn0 = (wid >> 1) * 64;
    const int m0 = blockIdx.x * 128, c = blockIdx.y;
    const int prow = tid >> 3, pg = tid & 7;   // prow 0..31
    const uint32_t pdst = sb + RING + prow * 128 + ((pg ^ (prow & 7)) << 4);

// L0 produce: step = 0..7 (nchunk = step>>2, t = step&3)
#define PRODUCE_L0(s, step) do {                                               \
    const int _t = (step) & 3, _nc = (step) >> 2;                              \
    _Pragma("unroll")                                                          \
    for (int i = 0; i < 4; i++) {                                              \
        int row = prow + i * 32;                                               \
        CP16(pdst + (s) * STG + i * 4096,                                      \
             &g_xh[m0 + row][_t * 64 + pg * 8]);                               \
    }                                                                          \
    _Pragma("unroll")                                                          \
    for (int i = 0; i < 8; i++) {                                              \
        int row = prow + i * 32;                                               \
        CP16(pdst + (s) * STG + 16384 + i * 4096,                              \
             &g_w0h[c][_nc * 256 + row][_t * 64 + pg * 8]);                    \
    }                                                                          \
} while (0)

// L1 produce: B only (w1), step u = 0..7
#define PRODUCE_L1(s, u) do {                                                  \
    _Pragma("unroll")                                                          \
    for (int i = 0; i < 8; i++) {                                              \
        int row = prow + i * 32;                                               \
        CP16(pdst + (s) * STG + 16384 + i * 4096,                              \
             &g_w1h[c][row][(u) * 64 + pg * 8]);                               \
    }                                                                          \
} while (0)

    // two fp16 acc sets (one per k128 half), 128 b32 regs total
    uint32_t acch[2][4][8][2];
    ACC_ZERO();

    // =================== Layer 0 ===================
    PRODUCE_L0(0, 0); CP_COMMIT();

    #pragma unroll 1
    for (int s = 0; s < 8; s++) {
        CP_WAIT0();
        __syncthreads();
        if (s < 7) { PRODUCE_L0((s + 1) & 1, s + 1); }
        CP_COMMIT();
        const uint32_t sA = sb + RING + (s & 1) * STG;
        const uint32_t sB = sA + 16384;
        const int set = (s >> 1) & 1;             // k128 half within n-chunk
        #pragma unroll
        for (int s16 = 0; s16 < 4; s16++) {
            uint32_t afr[4][4], bfr[4][4];
            #pragma unroll
            for (int mt = 0; mt < 4; mt++) {
                int row = wm0 + mt * 16 + (lane & 7) + ((lane >> 3) & 1) * 8;
                int g   = s16 * 2 + (lane >> 4);
                LDSM4(afr[mt], sA + row * 128 + ((g ^ (row & 7)) << 4));
            }
            LOADB(sB);
            DOMMA(acch[set]);
        }

        if ((s & 3) == 3) {
            // epilogue for n-chunk (s>>2): combine halves, relu(+b0) -> fp16 -> smem h0
            const int nc = s >> 2;
            #pragma unroll
            for (int mt = 0; mt < 4; mt++) {
                #pragma unroll
                for (int ni = 0; ni < 8; ni++) {
                    const int n = nc * 256 + wn0 + ni * 8 + (lane & 3) * 2;
                    const float bn0 = b0g[c * H0n + n];
                    const float bn1 = b0g[c * H0n + n + 1];
                    #pragma unroll
                    for (int half = 0; half < 2; half++) {
                        const int m = wm0 + mt * 16 + (lane >> 2) + half * 8;
                        float2 pa = h2f2(acch[0][mt][ni][half]);
                        float2 pb = h2f2(acch[1][mt][ni][half]);
                        float v0 = fmaxf(pa.x + pb.x + bn0, 0.0f);
                        float v1 = fmaxf(pa.y + pb.y + bn1, 0.0f);
                        __half h0 = __float2half_rn(v0), h1 = __float2half_rn(v1);
                        uint32_t hp = (uint32_t)__half_as_ushort(h0)
                                    | ((uint32_t)__half_as_ushort(h1) << 16);
                        *(uint32_t*)(sm + H0S + m * 1024 + ((2 * n) ^ ((m & 7) << 4))) = hp;
                    }
                }
            }
            ACC_ZERO();
        }
    }

    __syncthreads();    // h0 tile complete & visible; ring fully free

    // =================== Layer 1 ===================
    PRODUCE_L1(0, 0); CP_COMMIT();

    #pragma unroll 1
    for (int u = 0; u < 8; u++) {
        CP_WAIT0();
        __syncthreads();
        if (u < 7) { PRODUCE_L1((u + 1) & 1, u + 1); }
        CP_COMMIT();
        const uint32_t sB = sb + RING + (u & 1) * STG + 16384;
        const int set = (u >> 2) & 1;             // k256 half
        #pragma unroll
        for (int s16 = 0; s16 < 4; s16++) {
            uint32_t afr[4][4], bfr[4][4];
            #pragma unroll
            for (int mt = 0; mt < 4; mt++) {
                int row = wm0 + mt * 16 + (lane & 7) + ((lane >> 3) & 1) * 8;
                int g   = u * 8 + s16 * 2 + (lane >> 4);      // k16-group 0..63
                LDSM4(afr[mt], sb + H0S + row * 1024 + (((uint32_t)g << 4) ^ ((row & 7) << 4)));
            }
            LOADB(sB);
            DOMMA(acch[set]);
        }
    }

    // =================== final epilogue: combine halves, relu(+b1).w2 + b2 ===================
    float s[8];
    #pragma unroll
    for (int i = 0; i < 8; i++) s[i] = 0.0f;
    #pragma unroll
    for (int mt = 0; mt < 4; mt++) {
        #pragma unroll
        for (int ni = 0; ni < 8; ni++) {
            const int n = wn0 + ni * 8 + (lane & 3) * 2;
            const float bn0 = b1g[c * H1n + n],  bn1 = b1g[c * H1n + n + 1];
            const float w0v = w2g[c * H1n + n],  w1v = w2g[c * H1n + n + 1];
            #pragma unroll
            for (int half = 0; half < 2; half++) {
                float2 pa = h2f2(acch[0][mt][ni][half]);
                float2 pb = h2f2(acch[1][mt][ni][half]);
                s[mt * 2 + half] += fmaxf(pa.x + pb.x + bn0, 0.0f) * w0v
                                  + fmaxf(pa.y + pb.y + bn1, 0.0f) * w1v;
            }
        }
    }
    #pragma unroll
    for (int i = 0; i < 8; i++) {
        s[i] += __shfl_xor_sync(0xFFFFFFFF, s[i], 1);
        s[i] += __shfl_xor_sync(0xFFFFFFFF, s[i], 2);
    }
    float* red = (float*)(sm + RING);   // reuse dead ring A-slot: [128][4]
    __syncthreads();
    if ((lane & 3) == 0) {
        #pragma unroll
        for (int mt = 0; mt < 4; mt++)
            #pragma unroll
            for (int half = 0; half < 2; half++) {
                int r = wm0 + mt * 16 + half * 8 + (lane >> 2);
                red[r * 4 + (wid >> 1)] = s[mt * 2 + half];
            }
    }
    __syncthreads();
    if (tid < 128) {
        float v = red[tid * 4] + red[tid * 4 + 1] + red[tid * 4 + 2] + red[tid * 4 + 3];
        out[(size_t)(m0 + tid) * Cn + c] = v + b2g[c];
    }
}

extern "C" void kernel_launch(void* const* d_in, const int* in_sizes, int n_in,
                              void* d_out, int out_size) {
    (void)in_sizes; (void)n_in; (void)out_size;
    const float* x  = (const float*)d_in[0];
    const float* W0 = (const float*)d_in[1];
    const float* b0 = (const float*)d_in[2];
    const float* W1 = (const float*)d_in[3];
    const float* b1 = (const float*)d_in[4];
    const float* W2 = (const float*)d_in[5];
    const float* b2 = (const float*)d_in[6];
    float* out = (float*)d_out;

    prep_all<<<3072, 256>>>(x, W0, W1);

    cudaFuncSetAttribute(fused, cudaFuncAttributeMaxDynamicSharedMemorySize, SMEM_TOTAL);
    fused<<<dim3(128, 8), 256, SMEM_TOTAL>>>(b0, b1, W2, b2, out);
}

// round 12
// speedup vs baseline: 3.4975x; 3.4975x over previous
#include <cuda_runtime.h>
#include <cuda_fp16.h>
#include <cstdint>

#define Bsz 16384
#define Cn  8
#define Dd  256
#define H0n 512
#define H1n 256

// ---------------- scratch (device statics) ----------------
__device__ __align__(16) __half g_xh  [Bsz][Dd];           // 8MB   x fp16
__device__ __align__(16) __half g_w0h [Cn][H0n][Dd];       // 2MB   w0 fp16
__device__ __align__(16) __half g_w1h [Cn][H1n][H0n];      // 2MB   w1 fp16

// ---------------- prep: x, w0, w1 convert, one launch ----------------
__device__ __forceinline__ uint4 cvt8h(const float* s) {
    uint32_t h[4];
    #pragma unroll
    for (int i = 0; i < 4; i++) {
        __half h0 = __float2half_rn(s[2*i]), h1 = __float2half_rn(s[2*i+1]);
        h[i] = (uint32_t)__half_as_ushort(h0) | ((uint32_t)__half_as_ushort(h1) << 16);
    }
    return make_uint4(h[0], h[1], h[2], h[3]);
}

__global__ void prep_all(const float* __restrict__ x,
                         const float* __restrict__ W0, const float* __restrict__ W1) {
    int u = blockIdx.x * blockDim.x + threadIdx.x;   // 786432 total
    float buf[8];
    if (u < 524288) {                                 // x
        int k8 = u & 31, b = u >> 5;
        *(float4*)(buf)   = *(const float4*)(x + (size_t)b * Dd + k8 * 8);
        *(float4*)(buf+4) = *(const float4*)(x + (size_t)b * Dd + k8 * 8 + 4);
        *(uint4*)&g_xh[b][k8 * 8] = cvt8h(buf);
    } else if (u < 655360) {                          // w0
        int v = u - 524288;
        int k8 = v & 31, n = (v >> 5) & 511, c = v >> 14;
        const float* src = W0 + ((size_t)c * H0n + n) * Dd + k8 * 8;
        *(float4*)(buf)   = *(const float4*)(src);
        *(float4*)(buf+4) = *(const float4*)(src + 4);
        *(uint4*)&g_w0h[c][n][k8 * 8] = cvt8h(buf);
    } else {                                          // w1
        int v = u - 655360;
        int k8 = v & 63, n = (v >> 6) & 255, c = v >> 14;
        const float* src = W1 + ((size_t)c * H1n + n) * H0n + k8 * 8;
        *(float4*)(buf)   = *(const float4*)(src);
        *(float4*)(buf+4) = *(const float4*)(src + 4);
        *(uint4*)&g_w1h[c][n][k8 * 8] = cvt8h(buf);
    }
}

// ---------------- machinery ----------------
__device__ __forceinline__ uint32_t smem_u32(const void* p) {
    uint32_t a;
    asm("{ .reg .u64 t; cvta.to.shared.u64 t, %1; cvt.u32.u64 %0, t; }" : "=r"(a) : "l"(p));
    return a;
}
#define CP16(dst, src) asm volatile("cp.async.cg.shared.global [%0], [%1], 16;" :: "r"(dst), "l"(src))
#define CP_COMMIT()    asm volatile("cp.async.commit_group;" ::: "memory")
#define CP_WAIT0()     asm volatile("cp.async.wait_group 0;" ::: "memory")
#define LDSM4(r, a) \
    asm volatile("ldmatrix.sync.aligned.m8n8.x4.shared.b16 {%0,%1,%2,%3}, [%4];" \
        : "=r"((r)[0]), "=r"((r)[1]), "=r"((r)[2]), "=r"((r)[3]) : "r"(a))
#define MMA(d, a, b0, b1) \
    asm volatile("mma.sync.aligned.m16n8k16.row.col.f32.f16.f16.f32 " \
        "{%0,%1,%2,%3}, {%4,%5,%6,%7}, {%8,%9}, {%0,%1,%2,%3};" \
        : "+f"((d)[0]), "+f"((d)[1]), "+f"((d)[2]), "+f"((d)[3]) \
        : "r"((a)[0]), "r"((a)[1]), "r"((a)[2]), "r"((a)[3]), "r"(b0), "r"(b1))

// ---- smem layout (bytes) ----
// h0 tile:  [0, 131072)              128 rows x 1024B (512 fp16), XOR-swizzled rows
// ring:     [131072, 229376)         2 stages x 48KB; stage: A 16KB @ +0, B 32KB @ +16384
// b0s:      [229376, 231424)         512 floats
// red:      reuses ring stage0 A-slot
#define H0S   0
#define RING  131072
#define STG   49152
#define B0OFF 229376
#define SMEM_TOTAL 231424

#define LOADB(sB) do {                                                         \
    _Pragma("unroll")                                                          \
    for (int ng = 0; ng < 4; ng++) {                                           \
        int row = wn0 + ng * 16 + (lane & 7) + ((lane >> 4) << 3);             \
        int g   = s16 * 2 + ((lane >> 3) & 1);                                 \
        LDSM4(bfr[ng], (sB) + row * 128 + ((g ^ (row & 7)) << 4));             \
    }                                                                          \
} while (0)

#define DOMMA() \
    _Pragma("unroll")                                                          \
    for (int mt = 0; mt < 4; mt++)                                             \
        _Pragma("unroll")                                                      \
        for (int ni = 0; ni < 8; ni++)                                         \
            MMA(acc[mt][ni], afr[mt], bfr[ni >> 1][(ni & 1) * 2],              \
                bfr[ni >> 1][(ni & 1) * 2 + 1])

#define ACC_ZERO()                                                             \
    _Pragma("unroll")                                                          \
    for (int a = 0; a < 4; a++)                                                \
        _Pragma("unroll")                                                      \
        for (int b = 0; b < 8; b++)                                            \
            _Pragma("unroll")                                                  \
            for (int r = 0; r < 4; r++) acc[a][b][r] = 0.0f;

// ============ fused: h0 = relu(x@w0^T+b0) in smem; out = relu(h0@w1^T+b1).w2 + b2 ============
__global__ void __launch_bounds__(256, 1)
fused(const float* __restrict__ b0g, const float* __restrict__ b1g,
      const float* __restrict__ w2g, const float* __restrict__ b2g,
      float* __restrict__ out)
{
    extern __shared__ __align__(128) uint8_t sm[];
    const uint32_t sb = smem_u32(sm);
    const int tid = threadIdx.x, lane = tid & 31, wid = tid >> 5;
    const int wm0 = (wid & 1) * 64, wn0 = (wid >> 1) * 64;
    const int m0 = blockIdx.x * 128, c = blockIdx.y;
    const int prow = tid >> 3, pg = tid & 7;   // prow 0..31
    const uint32_t pdst = sb + RING + prow * 128 + ((pg ^ (prow & 7)) << 4);

    float* b0s = (float*)(sm + B0OFF);
    b0s[tid]       = b0g[c * H0n + tid];
    b0s[tid + 256] = b0g[c * H0n + tid + 256];

// L0 produce: step = 0..7 (nchunk = step>>2, t = step&3)
#define PRODUCE_L0(s, step) do {                                               \
    const int _t = (step) & 3, _nc = (step) >> 2;                              \
    _Pragma("unroll")                                                          \
    for (int i = 0; i < 4; i++) {                                              \
        int row = prow + i * 32;                                               \
        CP16(pdst + (s) * STG + i * 4096,                                      \
             &g_xh[m0 + row][_t * 64 + pg * 8]);                               \
    }                                                                          \
    _Pragma("unroll")                                                          \
    for (int i = 0; i < 8; i++) {                                              \
        int row = prow + i * 32;                                               \
        CP16(pdst + (s) * STG + 16384 + i * 4096,                              \
             &g_w0h[c][_nc * 256 + row][_t * 64 + pg * 8]);                    \
    }                                                                          \
} while (0)

// L1 produce: B only (w1), step u = 0..7
#define PRODUCE_L1(s, u) do {                                                  \
    _Pragma("unroll")                                                          \
    for (int i = 0; i < 8; i++) {                                              \
        int row = prow + i * 32;                                               \
        CP16(pdst + (s) * STG + 16384 + i * 4096,                              \
             &g_w1h[c][row][(u) * 64 + pg * 8]);                               \
    }                                                                          \
} while (0)

    float acc[4][8][4];
    ACC_ZERO();

    // =================== Layer 0 ===================
    PRODUCE_L0(0, 0); CP_COMMIT();

    #pragma unroll 1
    for (int s = 0; s < 8; s++) {
        CP_WAIT0();
        __syncthreads();
        if (s < 7) { PRODUCE_L0((s + 1) & 1, s + 1); }
        else       { PRODUCE_L1((s + 1) & 1, 0); }     // prefetch L1 step 0 into stage 0
        CP_COMMIT();
        const uint32_t sA = sb + RING + (s & 1) * STG;
        const uint32_t sB = sA + 16384;
        #pragma unroll
        for (int s16 = 0; s16 < 4; s16++) {
            uint32_t afr[4][4], bfr[4][4];
            #pragma unroll
            for (int mt = 0; mt < 4; mt++) {
                int row = wm0 + mt * 16 + (lane & 7) + ((lane >> 3) & 1) * 8;
                int g   = s16 * 2 + (lane >> 4);
                LDSM4(afr[mt], sA + row * 128 + ((g ^ (row & 7)) << 4));
            }
            LOADB(sB);
            DOMMA();
        }

        if ((s & 3) == 3) {
            // epilogue for n-chunk (s>>2): relu(+b0) -> fp16 -> smem h0 tile
            const int nc = s >> 2;
            #pragma unroll
            for (int mt = 0; mt < 4; mt++) {
                #pragma unroll
                for (int ni = 0; ni < 8; ni++) {
                    const int n = nc * 256 + wn0 + ni * 8 + (lane & 3) * 2;
                    const float bn0 = b0s[n], bn1 = b0s[n + 1];
                    #pragma unroll
                    for (int half = 0; half < 2; half++) {
                        const int m = wm0 + mt * 16 + (lane >> 2) + half * 8;
                        float v0 = fmaxf(acc[mt][ni][half * 2 + 0] + bn0, 0.0f);
                        float v1 = fmaxf(acc[mt][ni][half * 2 + 1] + bn1, 0.0f);
                        __half h0 = __float2half_rn(v0), h1 = __float2half_rn(v1);
                        uint32_t hp = (uint32_t)__half_as_ushort(h0)
                                    | ((uint32_t)__half_as_ushort(h1) << 16);
                        *(uint32_t*)(sm + H0S + m * 1024 + ((2 * n) ^ ((m & 7) << 4))) = hp;
                    }
                }
            }
            ACC_ZERO();
        }
    }

    __syncthreads();    // h0 tile complete & visible

    // =================== Layer 1 ===================
    #pragma unroll 1
    for (int u = 0; u < 8; u++) {
        CP_WAIT0();
        __syncthreads();
        if (u < 7) { PRODUCE_L1((u + 1) & 1, u + 1); }
        CP_COMMIT();
        const uint32_t sB = sb + RING + (u & 1) * STG + 16384;
        #pragma unroll
        for (int s16 = 0; s16 < 4; s16++) {
            uint32_t afr[4][4], bfr[4][4];
            #pragma unroll
            for (int mt = 0; mt < 4; mt++) {
                int row = wm0 + mt * 16 + (lane & 7) + ((lane >> 3) & 1) * 8;
                int g   = u * 8 + s16 * 2 + (lane >> 4);      // k16-group 0..63
                LDSM4(afr[mt], sb + H0S + row * 1024 + (((uint32_t)g << 4) ^ ((row & 7) << 4)));
            }
            LOADB(sB);
            DOMMA();
        }
    }

    // =================== final epilogue: relu(+b1).w2 + b2 ===================
    float s[8];
    #pragma unroll
    for (int i = 0; i < 8; i++) s[i] = 0.0f;
    #pragma unroll
    for (int mt = 0; mt < 4; mt++) {
        #pragma unroll
        for (int ni = 0; ni < 8; ni++) {
            const int n = wn0 + ni * 8 + (lane & 3) * 2;
            const float bn0 = b1g[c * H1n + n],  bn1 = b1g[c * H1n + n + 1];
            const float w0v = w2g[c * H1n + n],  w1v = w2g[c * H1n + n + 1];
            s[mt * 2 + 0] += fmaxf(acc[mt][ni][0] + bn0, 0.0f) * w0v
                           + fmaxf(acc[mt][ni][1] + bn1, 0.0f) * w1v;
            s[mt * 2 + 1] += fmaxf(acc[mt][ni][2] + bn0, 0.0f) * w0v
                           + fmaxf(acc[mt][ni][3] + bn1, 0.0f) * w1v;
        }
    }
    #pragma unroll
    for (int i = 0; i < 8; i++) {
        s[i] += __shfl_xor_sync(0xFFFFFFFF, s[i], 1);
        s[i] += __shfl_xor_sync(0xFFFFFFFF, s[i], 2);
    }
    float* red = (float*)(sm + RING);   // reuse dead ring A-slot: [128][4]
    __syncthreads();
    if ((lane & 3) == 0) {
        #pragma unroll
        for (int mt = 0; mt < 4; mt++)
            #pragma unroll
            for (int half = 0; half < 2; half++) {
                int r = wm0 + mt * 16 + half * 8 + (lane >> 2);
                red[r * 4 + (wid >> 1)] = s[mt * 2 + half];
            }
    }
    __syncthreads();
    if (tid < 128) {
        float v = red[tid * 4] + red[tid * 4 + 1] + red[tid * 4 + 2] + red[tid * 4 + 3];
        out[(size_t)(m0 + tid) * Cn + c] = v + b2g[c];
    }
}

extern "C" void kernel_launch(void* const* d_in, const int* in_sizes, int n_in,
                              void* d_out, int out_size) {
    (void)in_sizes; (void)n_in; (void)out_size;
    const float* x  = (const float*)d_in[0];
    const float* W0 = (const float*)d_in[1];
    const float* b0 = (const float*)d_in[2];
    const float* W1 = (const float*)d_in[3];
    const float* b1 = (const float*)d_in[4];
    const float* W2 = (const float*)d_in[5];
    const float* b2 = (const float*)d_in[6];
    float* out = (float*)d_out;

    prep_all<<<3072, 256>>>(x, W0, W1);

    cudaFuncSetAttribute(fused, cudaFuncAttributeMaxDynamicSharedMemorySize, SMEM_TOTAL);
    fused<<<dim3(128, 8), 256, SMEM_TOTAL>>>(b0, b1, W2, b2, out);
}

// round 13
// speedup vs baseline: 3.6871x; 1.0542x over previous
#include <cuda_runtime.h>
#include <cuda_fp16.h>
#include <cstdint>

#define Bsz 16384
#define Cn  8
#define Dd  256
#define H0n 512
#define H1n 256
#define NTILES 1024

// ---------------- scratch (device statics) ----------------
__device__ __align__(16) __half g_xh  [Bsz][Dd];           // 8MB   x fp16
__device__ __align__(16) __half g_w0h [Cn][H0n][Dd];       // 2MB   w0 fp16
__device__ __align__(16) __half g_w1h [Cn][H1n][H0n];      // 2MB   w1 fp16

// ---------------- prep: x, w0, w1 convert, one launch ----------------
__device__ __forceinline__ uint4 cvt8h(const float* s) {
    uint32_t h[4];
    #pragma unroll
    for (int i = 0; i < 4; i++) {
        __half h0 = __float2half_rn(s[2*i]), h1 = __float2half_rn(s[2*i+1]);
        h[i] = (uint32_t)__half_as_ushort(h0) | ((uint32_t)__half_as_ushort(h1) << 16);
    }
    return make_uint4(h[0], h[1], h[2], h[3]);
}

__global__ void prep_all(const float* __restrict__ x,
                         const float* __restrict__ W0, const float* __restrict__ W1) {
    int u = blockIdx.x * blockDim.x + threadIdx.x;   // 786432 total
    float buf[8];
    if (u < 524288) {                                 // x
        int k8 = u & 31, b = u >> 5;
        *(float4*)(buf)   = *(const float4*)(x + (size_t)b * Dd + k8 * 8);
        *(float4*)(buf+4) = *(const float4*)(x + (size_t)b * Dd + k8 * 8 + 4);
        *(uint4*)&g_xh[b][k8 * 8] = cvt8h(buf);
    } else if (u < 655360) {                          // w0
        int v = u - 524288;
        int k8 = v & 31, n = (v >> 5) & 511, c = v >> 14;
        const float* src = W0 + ((size_t)c * H0n + n) * Dd + k8 * 8;
        *(float4*)(buf)   = *(const float4*)(src);
        *(float4*)(buf+4) = *(const float4*)(src + 4);
        *(uint4*)&g_w0h[c][n][k8 * 8] = cvt8h(buf);
    } else {                                          // w1
        int v = u - 655360;
        int k8 = v & 63, n = (v >> 6) & 255, c = v >> 14;
        const float* src = W1 + ((size_t)c * H1n + n) * H0n + k8 * 8;
        *(float4*)(buf)   = *(const float4*)(src);
        *(float4*)(buf+4) = *(const float4*)(src + 4);
        *(uint4*)&g_w1h[c][n][k8 * 8] = cvt8h(buf);
    }
}

// ---------------- machinery ----------------
__device__ __forceinline__ uint32_t smem_u32(const void* p) {
    uint32_t a;
    asm("{ .reg .u64 t; cvta.to.shared.u64 t, %1; cvt.u32.u64 %0, t; }" : "=r"(a) : "l"(p));
    return a;
}
#define CP16(dst, src) asm volatile("cp.async.cg.shared.global [%0], [%1], 16;" :: "r"(dst), "l"(src))
#define CP_COMMIT()    asm volatile("cp.async.commit_group;" ::: "memory")
#define CP_WAIT0()     asm volatile("cp.async.wait_group 0;" ::: "memory")
#define LDSM4(r, a) \
    asm volatile("ldmatrix.sync.aligned.m8n8.x4.shared.b16 {%0,%1,%2,%3}, [%4];" \
        : "=r"((r)[0]), "=r"((r)[1]), "=r"((r)[2]), "=r"((r)[3]) : "r"(a))
#define MMA(d, a, b0, b1) \
    asm volatile("mma.sync.aligned.m16n8k16.row.col.f32.f16.f16.f32 " \
        "{%0,%1,%2,%3}, {%4,%5,%6,%7}, {%8,%9}, {%0,%1,%2,%3};" \
        : "+f"((d)[0]), "+f"((d)[1]), "+f"((d)[2]), "+f"((d)[3]) \
        : "r"((a)[0]), "r"((a)[1]), "r"((a)[2]), "r"((a)[3]), "r"(b0), "r"(b1))

// ---- smem layout (bytes) ----
// h0 tile:  [0, 131072)        128 rows x 1024B (512 fp16), XOR-swizzled rows
// ring:     [131072, 229376)   2 stages x 48KB; stage: A 16KB @ +0, B 32KB @ +16384
// red:      [229376, 231424)   dedicated (ring stage0 is live with cross-tile prefetch)
#define H0S    0
#define RING   131072
#define STG    49152
#define REDOFF 229376
#define SMEM_TOTAL 231424

#define LOADB(sB) do {                                                         \
    _Pragma("unroll")                                                          \
    for (int ng = 0; ng < 4; ng++) {                                           \
        int row = wn0 + ng * 16 + (lane & 7) + ((lane >> 4) << 3);             \
        int g   = s16 * 2 + ((lane >> 3) & 1);                                 \
        LDSM4(bfr[ng], (sB) + row * 128 + ((g ^ (row & 7)) << 4));             \
    }                                                                          \
} while (0)

#define DOMMA() \
    _Pragma("unroll")                                                          \
    for (int mt = 0; mt < 4; mt++)                                             \
        _Pragma("unroll")                                                      \
        for (int ni = 0; ni < 8; ni++)                                         \
            MMA(acc[mt][ni], afr[mt], bfr[ni >> 1][(ni & 1) * 2],              \
                bfr[ni >> 1][(ni & 1) * 2 + 1])

#define ACC_ZERO()                                                             \
    _Pragma("unroll")                                                          \
    for (int a = 0; a < 4; a++)                                                \
        _Pragma("unroll")                                                      \
        for (int b = 0; b < 8; b++)                                            \
            _Pragma("unroll")                                                  \
            for (int r = 0; r < 4; r++) acc[a][b][r] = 0.0f;

// ============ persistent fused kernel ============
__global__ void __launch_bounds__(256, 1)
fused(const float* __restrict__ b0g, const float* __restrict__ b1g,
      const float* __restrict__ w2g, const float* __restrict__ b2g,
      float* __restrict__ out)
{
    extern __shared__ __align__(128) uint8_t sm[];
    const uint32_t sb = smem_u32(sm);
    const int tid = threadIdx.x, lane = tid & 31, wid = tid >> 5;
    const int wm0 = (wid & 1) * 64, wn0 = (wid >> 1) * 64;
    const int prow = tid >> 3, pg = tid & 7;   // prow 0..31
    const uint32_t pdst = sb + RING + prow * 128 + ((pg ^ (prow & 7)) << 4);
    float* red = (float*)(sm + REDOFF);

// L0 produce for tile (_m0,_c): step = 0..7 (nchunk = step>>2, t = step&3)
#define PRODUCE_L0(s, step, _m0, _c) do {                                      \
    const int _t = (step) & 3, _nc = (step) >> 2;                              \
    _Pragma("unroll")                                                          \
    for (int i = 0; i < 4; i++) {                                              \
        int row = prow + i * 32;                                               \
        CP16(pdst + (s) * STG + i * 4096,                                      \
             &g_xh[(_m0) + row][_t * 64 + pg * 8]);                            \
    }                                                                          \
    _Pragma("unroll")                                                          \
    for (int i = 0; i < 8; i++) {                                              \
        int row = prow + i * 32;                                               \
        CP16(pdst + (s) * STG + 16384 + i * 4096,                              \
             &g_w0h[(_c)][_nc * 256 + row][_t * 64 + pg * 8]);                 \
    }                                                                          \
} while (0)

// L1 produce: B only (w1), step u = 0..7
#define PRODUCE_L1(s, u, _c) do {                                              \
    _Pragma("unroll")                                                          \
    for (int i = 0; i < 8; i++) {                                              \
        int row = prow + i * 32;                                               \
        CP16(pdst + (s) * STG + 16384 + i * 4096,                              \
             &g_w1h[(_c)][row][(u) * 64 + pg * 8]);                            \
    }                                                                          \
} while (0)

    float acc[4][8][4];
    ACC_ZERO();

    // first tile prologue
    {
        const int tile0 = blockIdx.x;
        if (tile0 < NTILES) {
            PRODUCE_L0(0, 0, (tile0 & 127) * 128, tile0 >> 7);
            CP_COMMIT();
        }
    }

    #pragma unroll 1
    for (int tile = blockIdx.x; tile < NTILES; tile += gridDim.x) {
        const int m0 = (tile & 127) * 128, c = tile >> 7;
        const int ntile = tile + gridDim.x;

        // =================== Layer 0 ===================
        #pragma unroll 1
        for (int s = 0; s < 8; s++) {
            CP_WAIT0();
            __syncthreads();
            if (s < 7) { PRODUCE_L0((s + 1) & 1, s + 1, m0, c); }
            else       { PRODUCE_L1((s + 1) & 1, 0, c); }   // L1 step 0 -> stage 0
            CP_COMMIT();
            const uint32_t sA = sb + RING + (s & 1) * STG;
            const uint32_t sB = sA + 16384;
            #pragma unroll
            for (int s16 = 0; s16 < 4; s16++) {
                uint32_t afr[4][4], bfr[4][4];
                #pragma unroll
                for (int mt = 0; mt < 4; mt++) {
                    int row = wm0 + mt * 16 + (lane & 7) + ((lane >> 3) & 1) * 8;
                    int g   = s16 * 2 + (lane >> 4);
                    LDSM4(afr[mt], sA + row * 128 + ((g ^ (row & 7)) << 4));
                }
                LOADB(sB);
                DOMMA();
            }

            if ((s & 3) == 3) {
                // epilogue for n-chunk (s>>2): relu(+b0) -> fp16 -> smem h0 tile
                const int nc = s >> 2;
                #pragma unroll
                for (int mt = 0; mt < 4; mt++) {
                    #pragma unroll
                    for (int ni = 0; ni < 8; ni++) {
                        const int n = nc * 256 + wn0 + ni * 8 + (lane & 3) * 2;
                        const float bn0 = b0g[c * H0n + n];
                        const float bn1 = b0g[c * H0n + n + 1];
                        #pragma unroll
                        for (int half = 0; half < 2; half++) {
                            const int m = wm0 + mt * 16 + (lane >> 2) + half * 8;
                            float v0 = fmaxf(acc[mt][ni][half * 2 + 0] + bn0, 0.0f);
                            float v1 = fmaxf(acc[mt][ni][half * 2 + 1] + bn1, 0.0f);
                            __half h0 = __float2half_rn(v0), h1 = __float2half_rn(v1);
                            uint32_t hp = (uint32_t)__half_as_ushort(h0)
                                        | ((uint32_t)__half_as_ushort(h1) << 16);
                            *(uint32_t*)(sm + H0S + m * 1024 + ((2 * n) ^ ((m & 7) << 4))) = hp;
                        }
                    }
                }
                ACC_ZERO();
            }
        }

        __syncthreads();    // h0 tile complete & visible

        // =================== Layer 1 ===================
        #pragma unroll 1
        for (int u = 0; u < 8; u++) {
            CP_WAIT0();
            __syncthreads();
            if (u < 7)              { PRODUCE_L1((u + 1) & 1, u + 1, c); }
            else if (ntile < NTILES){ PRODUCE_L0((u + 1) & 1, 0,
                                                 (ntile & 127) * 128, ntile >> 7); }
            CP_COMMIT();
            const uint32_t sB = sb + RING + (u & 1) * STG + 16384;
            #pragma unroll
            for (int s16 = 0; s16 < 4; s16++) {
                uint32_t afr[4][4], bfr[4][4];
                #pragma unroll
                for (int mt = 0; mt < 4; mt++) {
                    int row = wm0 + mt * 16 + (lane & 7) + ((lane >> 3) & 1) * 8;
                    int g   = u * 8 + s16 * 2 + (lane >> 4);      // k16-group 0..63
                    LDSM4(afr[mt], sb + H0S + row * 1024 + (((uint32_t)g << 4) ^ ((row & 7) << 4)));
                }
                LOADB(sB);
                DOMMA();
            }
        }

        // =================== final epilogue: relu(+b1).w2 + b2 ===================
        float s[8];
        #pragma unroll
        for (int i = 0; i < 8; i++) s[i] = 0.0f;
        #pragma unroll
        for (int mt = 0; mt < 4; mt++) {
            #pragma unroll
            for (int ni = 0; ni < 8; ni++) {
                const int n = wn0 + ni * 8 + (lane & 3) * 2;
                const float bn0 = b1g[c * H1n + n],  bn1 = b1g[c * H1n + n + 1];
                const float w0v = w2g[c * H1n + n],  w1v = w2g[c * H1n + n + 1];
                s[mt * 2 + 0] += fmaxf(acc[mt][ni][0] + bn0, 0.0f) * w0v
                               + fmaxf(acc[mt][ni][1] + bn1, 0.0f) * w1v;
                s[mt * 2 + 1] += fmaxf(acc[mt][ni][2] + bn0, 0.0f) * w0v
                               + fmaxf(acc[mt][ni][3] + bn1, 0.0f) * w1v;
            }
        }
        #pragma unroll
        for (int i = 0; i < 8; i++) {
            s[i] += __shfl_xor_sync(0xFFFFFFFF, s[i], 1);
            s[i] += __shfl_xor_sync(0xFFFFFFFF, s[i], 2);
        }
        __syncthreads();
        if ((lane & 3) == 0) {
            #pragma unroll
            for (int mt = 0; mt < 4; mt++)
                #pragma unroll
                for (int half = 0; half < 2; half++) {
                    int r = wm0 + mt * 16 + half * 8 + (lane >> 2);
                    red[r * 4 + (wid >> 1)] = s[mt * 2 + half];
                }
        }
        __syncthreads();
        if (tid < 128) {
            float v = red[tid * 4] + red[tid * 4 + 1] + red[tid * 4 + 2] + red[tid * 4 + 3];
            out[(size_t)(m0 + tid) * Cn + c] = v + b2g[c];
        }
        ACC_ZERO();
    }
}

extern "C" void kernel_launch(void* const* d_in, const int* in_sizes, int n_in,
                              void* d_out, int out_size) {
    (void)in_sizes; (void)n_in; (void)out_size;
    const float* x  = (const float*)d_in[0];
    const float* W0 = (const float*)d_in[1];
    const float* b0 = (const float*)d_in[2];
    const float* W1 = (const float*)d_in[3];
    const float* b1 = (const float*)d_in[4];
    const float* W2 = (const float*)d_in[5];
    const float* b2 = (const float*)d_in[6];
    float* out = (float*)d_out;

    prep_all<<<3072, 256>>>(x, W0, W1);

    static int nsm = 0;
    if (nsm == 0) {
        cudaDeviceGetAttribute(&nsm, cudaDevAttrMultiProcessorCount, 0);
        if (nsm <= 0) nsm = 148;
    }
    cudaFuncSetAttribute(fused, cudaFuncAttributeMaxDynamicSharedMemorySize, SMEM_TOTAL);
    fused<<<nsm, 256, SMEM_TOTAL>>>(b0, b1, W2, b2, out);
}